// round 1
// baseline (speedup 1.0000x reference)
#include <cuda_runtime.h>

#define EPS 1e-8f

__global__ void __launch_bounds__(256)
featnorm_kernel(const float* __restrict__ mag,
                const float* __restrict__ s0,
                const float* __restrict__ weights,
                const float* __restrict__ bias,
                const float* __restrict__ alpha,
                float* __restrict__ out,
                int B, int T, int F)
{
    int tid = blockIdx.x * blockDim.x + threadIdx.x;
    int total = B * F;
    if (tid >= total) return;

    int b = tid / F;
    int f = tid - b * F;

    // a = sigmoid(alpha[f]); per-feature constants
    float al = alpha[f];
    float a  = 1.0f / (1.0f + __expf(-al));
    float om = 1.0f - a;
    float wf = weights[f];
    float bf = bias[f];

    float s = s0[tid];   // s is [B, F], tid == b*F + f

    const float* __restrict__ mp = mag + (size_t)b * T * F + f;
    float* __restrict__ op       = out + (size_t)b * T * F + f;

    // Main loop: unroll 8 so the 8 independent LDGs are front-batched
    // (EMA carry chain depends only on s, not on the loads).
    int t = 0;
    int T8 = T & ~7;
    for (; t < T8; t += 8) {
        float m0 = mp[0 * F];
        float m1 = mp[1 * F];
        float m2 = mp[2 * F];
        float m3 = mp[3 * F];
        float m4 = mp[4 * F];
        float m5 = mp[5 * F];
        float m6 = mp[6 * F];
        float m7 = mp[7 * F];
        mp += 8 * F;

        float o0, o1, o2, o3, o4, o5, o6, o7;

        s = fmaf(m0 * m0, a, s * om);
        o0 = __fdividef(m0, sqrtf(s) + EPS) * wf + bf;
        s = fmaf(m1 * m1, a, s * om);
        o1 = __fdividef(m1, sqrtf(s) + EPS) * wf + bf;
        s = fmaf(m2 * m2, a, s * om);
        o2 = __fdividef(m2, sqrtf(s) + EPS) * wf + bf;
        s = fmaf(m3 * m3, a, s * om);
        o3 = __fdividef(m3, sqrtf(s) + EPS) * wf + bf;
        s = fmaf(m4 * m4, a, s * om);
        o4 = __fdividef(m4, sqrtf(s) + EPS) * wf + bf;
        s = fmaf(m5 * m5, a, s * om);
        o5 = __fdividef(m5, sqrtf(s) + EPS) * wf + bf;
        s = fmaf(m6 * m6, a, s * om);
        o6 = __fdividef(m6, sqrtf(s) + EPS) * wf + bf;
        s = fmaf(m7 * m7, a, s * om);
        o7 = __fdividef(m7, sqrtf(s) + EPS) * wf + bf;

        op[0 * F] = o0;
        op[1 * F] = o1;
        op[2 * F] = o2;
        op[3 * F] = o3;
        op[4 * F] = o4;
        op[5 * F] = o5;
        op[6 * F] = o6;
        op[7 * F] = o7;
        op += 8 * F;
    }
    for (; t < T; t++) {
        float m = *mp; mp += F;
        s = fmaf(m * m, a, s * om);
        *op = __fdividef(m, sqrtf(s) + EPS) * wf + bf;
        op += F;
    }
}

extern "C" void kernel_launch(void* const* d_in, const int* in_sizes, int n_in,
                              void* d_out, int out_size)
{
    const float* mag     = (const float*)d_in[0];  // [B, T, F]
    const float* s0      = (const float*)d_in[1];  // [B, F]
    const float* weights = (const float*)d_in[2];  // [1, 1, F]
    const float* bias    = (const float*)d_in[3];  // [1, 1, F]
    const float* alpha   = (const float*)d_in[4];  // [1, F]
    float* out = (float*)d_out;

    int F  = in_sizes[4];              // alpha: [1, F]
    int BF = in_sizes[1];              // s: [B, F]
    int B  = BF / F;
    int T  = in_sizes[0] / BF;         // mag: [B, T, F]

    int threads = 256;
    int blocks  = (BF + threads - 1) / threads;
    featnorm_kernel<<<blocks, threads>>>(mag, s0, weights, bias, alpha, out, B, T, F);
}

// round 3
// speedup vs baseline: 2.1634x; 2.1634x over previous
#include <cuda_runtime.h>
#include <math.h>

#define EPS 1e-8f

// Scratch for inter-chunk carries: [C][B][F] layout.
#define MAX_CARRY (1 << 23)
__device__ float g_carry[MAX_CARRY];

// ---------------------------------------------------------------------------
// Phase 1: thread = (b, chunk k, f). Chunk's EMA contribution from state 0:
//   s = s*om + a*p, starting s=0.
// ---------------------------------------------------------------------------
__global__ void __launch_bounds__(256)
phase1_kernel(const float* __restrict__ mag,
              const float* __restrict__ alpha,
              int B, int T, int F, int C, int L)
{
    int tid = blockIdx.x * blockDim.x + threadIdx.x;
    int total = B * C * F;
    if (tid >= total) return;

    int f  = tid % F;
    int bk = tid / F;          // b*C + k
    int k  = bk % C;
    int b  = bk / C;

    int t0  = k * L;
    int len = T - t0; if (len > L) len = L;
    if (len <= 0) { g_carry[((size_t)k * B + b) * F + f] = 0.0f; return; }

    float a  = 1.0f / (1.0f + expf(-alpha[f]));
    float om = 1.0f - a;

    const float* __restrict__ mp = mag + ((size_t)b * T + t0) * F + f;

    float s = 0.0f;
    int i = 0;
    int len8 = len & ~7;
    for (; i < len8; i += 8) {
        float m0 = mp[0 * F];
        float m1 = mp[1 * F];
        float m2 = mp[2 * F];
        float m3 = mp[3 * F];
        float m4 = mp[4 * F];
        float m5 = mp[5 * F];
        float m6 = mp[6 * F];
        float m7 = mp[7 * F];
        mp += 8 * F;
        s = fmaf(m0 * m0, a, s * om);
        s = fmaf(m1 * m1, a, s * om);
        s = fmaf(m2 * m2, a, s * om);
        s = fmaf(m3 * m3, a, s * om);
        s = fmaf(m4 * m4, a, s * om);
        s = fmaf(m5 * m5, a, s * om);
        s = fmaf(m6 * m6, a, s * om);
        s = fmaf(m7 * m7, a, s * om);
    }
    for (; i < len; i++) {
        float m = *mp; mp += F;
        s = fmaf(m * m, a, s * om);
    }

    g_carry[((size_t)k * B + b) * F + f] = s;
}

// ---------------------------------------------------------------------------
// Phase 2: thread = (b, chunk k, f). Reconstruct incoming state from s0 and
// carries of chunks 0..k-1 (each full length L), then emit outputs.
// ---------------------------------------------------------------------------
__global__ void __launch_bounds__(256)
phase2_kernel(const float* __restrict__ mag,
              const float* __restrict__ s0,
              const float* __restrict__ weights,
              const float* __restrict__ bias,
              const float* __restrict__ alpha,
              float* __restrict__ out,
              int B, int T, int F, int C, int L)
{
    int tid = blockIdx.x * blockDim.x + threadIdx.x;
    int total = B * C * F;
    if (tid >= total) return;

    int f  = tid % F;
    int bk = tid / F;
    int k  = bk % C;
    int b  = bk / C;

    int t0  = k * L;
    int len = T - t0; if (len > L) len = L;
    if (len <= 0) return;

    float a  = 1.0f / (1.0f + expf(-alpha[f]));
    float om = 1.0f - a;
    float wf = weights[f];
    float bf = bias[f];

    // incoming state: s = s0; for j < k: s = s*om^L + c_j
    float s = s0[b * F + f];
    if (k > 0) {
        float omL = powf(om, (float)L);
        const float* __restrict__ cp = g_carry + (size_t)b * F + f;
        for (int j = 0; j < k; j++) {
            s = fmaf(s, omL, cp[(size_t)j * B * F]);
        }
    }

    const float* __restrict__ mp = mag + ((size_t)b * T + t0) * F + f;
    float* __restrict__ op       = out + ((size_t)b * T + t0) * F + f;

    int i = 0;
    int len8 = len & ~7;
    for (; i < len8; i += 8) {
        float m0 = mp[0 * F];
        float m1 = mp[1 * F];
        float m2 = mp[2 * F];
        float m3 = mp[3 * F];
        float m4 = mp[4 * F];
        float m5 = mp[5 * F];
        float m6 = mp[6 * F];
        float m7 = mp[7 * F];
        mp += 8 * F;

        float o0, o1, o2, o3, o4, o5, o6, o7;
        s = fmaf(m0 * m0, a, s * om);
        o0 = __fdividef(m0, sqrtf(s) + EPS) * wf + bf;
        s = fmaf(m1 * m1, a, s * om);
        o1 = __fdividef(m1, sqrtf(s) + EPS) * wf + bf;
        s = fmaf(m2 * m2, a, s * om);
        o2 = __fdividef(m2, sqrtf(s) + EPS) * wf + bf;
        s = fmaf(m3 * m3, a, s * om);
        o3 = __fdividef(m3, sqrtf(s) + EPS) * wf + bf;
        s = fmaf(m4 * m4, a, s * om);
        o4 = __fdividef(m4, sqrtf(s) + EPS) * wf + bf;
        s = fmaf(m5 * m5, a, s * om);
        o5 = __fdividef(m5, sqrtf(s) + EPS) * wf + bf;
        s = fmaf(m6 * m6, a, s * om);
        o6 = __fdividef(m6, sqrtf(s) + EPS) * wf + bf;
        s = fmaf(m7 * m7, a, s * om);
        o7 = __fdividef(m7, sqrtf(s) + EPS) * wf + bf;

        op[0 * F] = o0;
        op[1 * F] = o1;
        op[2 * F] = o2;
        op[3 * F] = o3;
        op[4 * F] = o4;
        op[5 * F] = o5;
        op[6 * F] = o6;
        op[7 * F] = o7;
        op += 8 * F;
    }
    for (; i < len; i++) {
        float m = *mp; mp += F;
        s = fmaf(m * m, a, s * om);
        *op = __fdividef(m, sqrtf(s) + EPS) * wf + bf;
        op += F;
    }
}

extern "C" void kernel_launch(void* const* d_in, const int* in_sizes, int n_in,
                              void* d_out, int out_size)
{
    const float* mag     = (const float*)d_in[0];  // [B, T, F]
    const float* s0      = (const float*)d_in[1];  // [B, F]
    const float* weights = (const float*)d_in[2];  // [1, 1, F]
    const float* bias    = (const float*)d_in[3];  // [1, 1, F]
    const float* alpha   = (const float*)d_in[4];  // [1, F]
    float* out = (float*)d_out;

    int F  = in_sizes[4];
    int BF = in_sizes[1];
    int B  = BF / F;
    int T  = in_sizes[0] / BF;

    // Fixed chunk length L; every chunk except possibly the last has exactly
    // L steps (required by the om^L recombination).
    int L = (T + 15) / 16;         // target ~16 chunks
    if (L < 1) L = 1;
    int C = (T + L - 1) / L;
    while ((size_t)C * B * F > (size_t)MAX_CARRY && L < T) {
        L *= 2;
        C = (T + L - 1) / L;
    }

    int total   = B * C * F;
    int threads = 256;
    int blocks  = (total + threads - 1) / threads;

    phase1_kernel<<<blocks, threads>>>(mag, alpha, B, T, F, C, L);
    phase2_kernel<<<blocks, threads>>>(mag, s0, weights, bias, alpha, out,
                                       B, T, F, C, L);
}

// round 4
// speedup vs baseline: 3.0583x; 1.4136x over previous
#include <cuda_runtime.h>
#include <math.h>

#define EPS 1e-8f

// Scratch for inter-chunk carries: [C][B][F] layout.
#define MAX_CARRY (1 << 23)
__device__ float g_carry[MAX_CARRY];

__device__ __forceinline__ float sqrt_approx(float x) {
    float r;
    asm("sqrt.approx.f32 %0, %1;" : "=f"(r) : "f"(x));
    return r;
}

__device__ __forceinline__ void store_cs(float* p, float v) {
    asm volatile("st.global.cs.f32 [%0], %1;" :: "l"(p), "f"(v) : "memory");
}

// ---------------------------------------------------------------------------
// Phase 1: thread = (b, chunk k, f). Chunk's EMA contribution from state 0.
// ---------------------------------------------------------------------------
__global__ void __launch_bounds__(256)
phase1_kernel(const float* __restrict__ mag,
              const float* __restrict__ alpha,
              int B, int T, int F, int C, int L)
{
    int tid = blockIdx.x * blockDim.x + threadIdx.x;
    int total = B * C * F;
    if (tid >= total) return;

    int f  = tid % F;
    int bk = tid / F;          // b*C + k
    int k  = bk % C;
    int b  = bk / C;

    int t0  = k * L;
    int len = T - t0; if (len > L) len = L;
    if (len <= 0) { g_carry[((size_t)k * B + b) * F + f] = 0.0f; return; }

    float a  = 1.0f / (1.0f + __expf(-alpha[f]));
    float om = 1.0f - a;

    const float* __restrict__ mp = mag + ((size_t)b * T + t0) * F + f;

    float s = 0.0f;
    int i = 0;
    int len8 = len & ~7;
    for (; i < len8; i += 8) {
        float m0 = mp[0 * F];
        float m1 = mp[1 * F];
        float m2 = mp[2 * F];
        float m3 = mp[3 * F];
        float m4 = mp[4 * F];
        float m5 = mp[5 * F];
        float m6 = mp[6 * F];
        float m7 = mp[7 * F];
        mp += 8 * F;
        s = fmaf(m0 * m0, a, s * om);
        s = fmaf(m1 * m1, a, s * om);
        s = fmaf(m2 * m2, a, s * om);
        s = fmaf(m3 * m3, a, s * om);
        s = fmaf(m4 * m4, a, s * om);
        s = fmaf(m5 * m5, a, s * om);
        s = fmaf(m6 * m6, a, s * om);
        s = fmaf(m7 * m7, a, s * om);
    }
    for (; i < len; i++) {
        float m = *mp; mp += F;
        s = fmaf(m * m, a, s * om);
    }

    g_carry[((size_t)k * B + b) * F + f] = s;
}

// ---------------------------------------------------------------------------
// Phase 2: thread = (b, chunk k, f). Reconstruct incoming state from s0 and
// carries of chunks 0..k-1 (each full length L), then emit outputs.
// ---------------------------------------------------------------------------
__global__ void __launch_bounds__(256)
phase2_kernel(const float* __restrict__ mag,
              const float* __restrict__ s0,
              const float* __restrict__ weights,
              const float* __restrict__ bias,
              const float* __restrict__ alpha,
              float* __restrict__ out,
              int B, int T, int F, int C, int L)
{
    int tid = blockIdx.x * blockDim.x + threadIdx.x;
    int total = B * C * F;
    if (tid >= total) return;

    int f  = tid % F;
    int bk = tid / F;
    int k  = bk % C;
    int b  = bk / C;

    int t0  = k * L;
    int len = T - t0; if (len > L) len = L;
    if (len <= 0) return;

    float a  = 1.0f / (1.0f + __expf(-alpha[f]));
    float om = 1.0f - a;
    float wf = weights[f];
    float bf = bias[f];

    // incoming state: s = s0; for j < k: s = s*om^L + c_j
    float s = s0[b * F + f];
    if (k > 0) {
        float omL = __powf(om, (float)L);
        const float* __restrict__ cp = g_carry + (size_t)b * F + f;
        for (int j = 0; j < k; j++) {
            s = fmaf(s, omL, cp[(size_t)j * B * F]);
        }
    }

    const float* __restrict__ mp = mag + ((size_t)b * T + t0) * F + f;
    float* __restrict__ op       = out + ((size_t)b * T + t0) * F + f;

    int i = 0;
    int len8 = len & ~7;
    for (; i < len8; i += 8) {
        float m0 = mp[0 * F];
        float m1 = mp[1 * F];
        float m2 = mp[2 * F];
        float m3 = mp[3 * F];
        float m4 = mp[4 * F];
        float m5 = mp[5 * F];
        float m6 = mp[6 * F];
        float m7 = mp[7 * F];
        mp += 8 * F;

        float o0, o1, o2, o3, o4, o5, o6, o7;
        s = fmaf(m0 * m0, a, s * om);
        o0 = __fdividef(m0, sqrt_approx(s) + EPS) * wf + bf;
        s = fmaf(m1 * m1, a, s * om);
        o1 = __fdividef(m1, sqrt_approx(s) + EPS) * wf + bf;
        s = fmaf(m2 * m2, a, s * om);
        o2 = __fdividef(m2, sqrt_approx(s) + EPS) * wf + bf;
        s = fmaf(m3 * m3, a, s * om);
        o3 = __fdividef(m3, sqrt_approx(s) + EPS) * wf + bf;
        s = fmaf(m4 * m4, a, s * om);
        o4 = __fdividef(m4, sqrt_approx(s) + EPS) * wf + bf;
        s = fmaf(m5 * m5, a, s * om);
        o5 = __fdividef(m5, sqrt_approx(s) + EPS) * wf + bf;
        s = fmaf(m6 * m6, a, s * om);
        o6 = __fdividef(m6, sqrt_approx(s) + EPS) * wf + bf;
        s = fmaf(m7 * m7, a, s * om);
        o7 = __fdividef(m7, sqrt_approx(s) + EPS) * wf + bf;

        store_cs(op + 0 * F, o0);
        store_cs(op + 1 * F, o1);
        store_cs(op + 2 * F, o2);
        store_cs(op + 3 * F, o3);
        store_cs(op + 4 * F, o4);
        store_cs(op + 5 * F, o5);
        store_cs(op + 6 * F, o6);
        store_cs(op + 7 * F, o7);
        op += 8 * F;
    }
    for (; i < len; i++) {
        float m = *mp; mp += F;
        s = fmaf(m * m, a, s * om);
        store_cs(op, __fdividef(m, sqrt_approx(s) + EPS) * wf + bf);
        op += F;
    }
}

extern "C" void kernel_launch(void* const* d_in, const int* in_sizes, int n_in,
                              void* d_out, int out_size)
{
    const float* mag     = (const float*)d_in[0];  // [B, T, F]
    const float* s0      = (const float*)d_in[1];  // [B, F]
    const float* weights = (const float*)d_in[2];  // [1, 1, F]
    const float* bias    = (const float*)d_in[3];  // [1, 1, F]
    const float* alpha   = (const float*)d_in[4];  // [1, F]
    float* out = (float*)d_out;

    int F  = in_sizes[4];
    int BF = in_sizes[1];
    int B  = BF / F;
    int T  = in_sizes[0] / BF;

    // Fixed chunk length L; every chunk except possibly the last has exactly
    // L steps (required by the om^L recombination).
    int L = (T + 31) / 32;         // target ~32 chunks
    if (L < 1) L = 1;
    int C = (T + L - 1) / L;
    while ((size_t)C * B * F > (size_t)MAX_CARRY && L < T) {
        L *= 2;
        C = (T + L - 1) / L;
    }

    int total   = B * C * F;
    int threads = 256;
    int blocks  = (total + threads - 1) / threads;

    phase1_kernel<<<blocks, threads>>>(mag, alpha, B, T, F, C, L);
    phase2_kernel<<<blocks, threads>>>(mag, s0, weights, bias, alpha, out,
                                       B, T, F, C, L);
}